// round 8
// baseline (speedup 1.0000x reference)
#include <cuda_runtime.h>
#include <cuda_fp16.h>
#include <cstdint>

#define NN 50000
#define NE 640000
#define DIM 128

// ---------------- scratch (device globals: allocation-free rule) ----------------
__device__ float  g_Ax[NN * DIM];            // A output, fp32
__device__ __half g_Dh[NN * DIM];            // D output, fp16
__device__ __half g_EB[NN * DIM * 2];        // interleaved: [node][c] -> {Ex[c], Bx[c]} (half2)
__device__ float  g_num[NN * DIM];
__device__ float  g_den[NN * DIM];
__device__ uint2  g_Wf[5][16 * 16 * 32];     // fragment-packed tf32 weights: A,B,D,E,C
__device__ int    g_i64;

// ---------------- helpers ----------------
__device__ __forceinline__ unsigned f2tf32(float f) {
    unsigned u;
    asm("cvt.rna.tf32.f32 %0, %1;" : "=r"(u) : "f"(f));
    return u;
}

__device__ __forceinline__ void mma_tf32(float c[4], const unsigned a[4],
                                         unsigned b0, unsigned b1) {
    asm volatile(
        "mma.sync.aligned.m16n8k8.row.col.f32.tf32.tf32.f32 "
        "{%0,%1,%2,%3}, {%4,%5,%6,%7}, {%8,%9}, {%0,%1,%2,%3};"
        : "+f"(c[0]), "+f"(c[1]), "+f"(c[2]), "+f"(c[3])
        : "r"(a[0]), "r"(a[1]), "r"(a[2]), "r"(a[3]), "r"(b0), "r"(b1));
}

__device__ __forceinline__ float sigmoidf_(float v) {
    return 1.0f / (1.0f + __expf(-v));
}

// 64x128x128 GEMM core. sA: [64][132] 32-bit operands in smem (tf32 or raw fp32 bits).
__device__ __forceinline__ void gemm_tile(const unsigned* sA, const uint2* __restrict__ Wf,
                                          float acc[2][4][4], int mBase, int nb,
                                          int r, int c, int lane) {
#pragma unroll 4
    for (int ks = 0; ks < 16; ks++) {
        uint2 b[4];
#pragma unroll
        for (int tj = 0; tj < 4; tj++)
            b[tj] = __ldg(&Wf[(ks * 16 + nb + tj) * 32 + lane]);
        unsigned a[2][4];
#pragma unroll
        for (int ti = 0; ti < 2; ti++) {
            const unsigned* ap = &sA[(mBase + ti * 16 + r) * 132 + ks * 8 + c];
            a[ti][0] = ap[0];
            a[ti][1] = ap[8 * 132];
            a[ti][2] = ap[4];
            a[ti][3] = ap[8 * 132 + 4];
        }
#pragma unroll
        for (int ti = 0; ti < 2; ti++)
#pragma unroll
            for (int tj = 0; tj < 4; tj++)
                mma_tf32(acc[ti][tj], a[ti], b[tj].x, b[tj].y);
    }
}

static const int SMEM_NODE = 64 * 132 * 4 + 64 * 132 * 2;  // 50688 B (node kernel)
static const int SMEM_EDGE = 64 * 132 * 4 + 64 * 132 * 2;  // 50688 B (edge kernel: sE + sR)

// ---------------- kernel 0: zero num/den ----------------
__global__ void zero_kernel() {
    size_t i = (size_t)blockIdx.x * blockDim.x + threadIdx.x;
    float4 z = make_float4(0.f, 0.f, 0.f, 0.f);
    ((float4*)g_num)[i] = z;
    ((float4*)g_den)[i] = z;
}

// ---------------- kernel 1: detect edge_index dtype ----------------
__global__ void detect_kernel(const unsigned* __restrict__ w) {
    unsigned acc = 0;
    for (int i = threadIdx.x; i < 1024; i += 32) acc |= w[2 * i + 1];
#pragma unroll
    for (int o = 16; o; o >>= 1) acc |= __shfl_xor_sync(0xffffffffu, acc, o);
    if (threadIdx.x == 0) g_i64 = (acc == 0) ? 1 : 0;
}

// ---------------- kernel 1b: pack weights into fragment layout (tf32) ----------------
__global__ void prep_kernel(const float* __restrict__ W0, const float* __restrict__ W1,
                            const float* __restrict__ W2, const float* __restrict__ W3,
                            const float* __restrict__ W4) {
    const float* Ws[5] = {W0, W1, W2, W3, W4};
    const int lane = threadIdx.x;
    const int g = blockIdx.x;      // ks*16+ng
    const int mat = blockIdx.y;
    const int ks = g >> 4, ng = g & 15;
    const int r = lane >> 2, c = lane & 3;
    const float* W = Ws[mat];
    const int n = ng * 8 + r;
    const int k = ks * 8 + c;
    uint2 v;
    v.x = f2tf32(W[n * DIM + k]);
    v.y = f2tf32(W[n * DIM + k + 4]);
    g_Wf[mat][g * 32 + lane] = v;
}

// ---------------- kernel 2: node GEMMs split by j-pair ----------------
// blockIdx.y==0: A (fp32 out) then D (half2 out). blockIdx.y==1: B (park smem) then E (combine->g_EB).
__global__ void __launch_bounds__(256, 4) node_gemm_kernel(
    const float* __restrict__ x,
    const float* __restrict__ b0, const float* __restrict__ b1,
    const float* __restrict__ b2, const float* __restrict__ b3) {
    extern __shared__ unsigned smem[];
    unsigned* sX = smem;                          // 64*132 words (tf32 x tile)
    __half*  sB = (__half*)(smem + 64 * 132);     // 64*132 halves (B outputs park)

    const int tid = threadIdx.x;
    const int m0 = blockIdx.x * 64;
    const int jp = blockIdx.y;  // 0: {A,D}, 1: {B,E}

    for (int i = tid; i < 64 * 32; i += 256) {
        int row = i >> 5, c4 = (i & 31) << 2;
        float4 v = make_float4(0.f, 0.f, 0.f, 0.f);
        if (m0 + row < NN) v = *(const float4*)&x[(size_t)(m0 + row) * DIM + c4];
        unsigned* p = &sX[row * 132 + c4];
        p[0] = f2tf32(v.x); p[1] = f2tf32(v.y); p[2] = f2tf32(v.z); p[3] = f2tf32(v.w);
    }
    __syncthreads();

    const int lane = tid & 31, wid = tid >> 5;
    const int r = lane >> 2, c = lane & 3;
    const int mBase = (wid & 1) * 32;
    const int nBase = (wid >> 1) * 32;
    const int nb = (wid >> 1) * 4;

#pragma unroll
    for (int jj = 0; jj < 2; jj++) {
        // j index mapping: jp0 -> {0:A, 2:D}; jp1 -> {1:B, 3:E}
        const int j = jp + jj * 2;
        const float* bias = (j == 0) ? b0 : (j == 1) ? b1 : (j == 2) ? b2 : b3;
        const uint2* Wf = g_Wf[j];

        float acc[2][4][4];
#pragma unroll
        for (int tj = 0; tj < 4; tj++) {
            int n0 = nBase + tj * 8 + c * 2;
            float bv0 = __ldg(&bias[n0]), bv1 = __ldg(&bias[n0 + 1]);
#pragma unroll
            for (int ti = 0; ti < 2; ti++) {
                acc[ti][tj][0] = bv0; acc[ti][tj][1] = bv1;
                acc[ti][tj][2] = bv0; acc[ti][tj][3] = bv1;
            }
        }

        gemm_tile(sX, Wf, acc, mBase, nb, r, c, lane);

#pragma unroll
        for (int ti = 0; ti < 2; ti++) {
#pragma unroll
            for (int half_i = 0; half_i < 2; half_i++) {
                const int lm = mBase + ti * 16 + r + half_i * 8;  // local row
                const int m = m0 + lm;                             // global row
                if (m >= NN) continue;
#pragma unroll
                for (int tj = 0; tj < 4; tj++) {
                    const int n0 = nBase + tj * 8 + c * 2;
                    const float v0 = acc[ti][tj][half_i * 2];
                    const float v1 = acc[ti][tj][half_i * 2 + 1];
                    if (j == 0) {
                        *(float2*)&g_Ax[(size_t)m * DIM + n0] = make_float2(v0, v1);
                    } else if (j == 1) {
                        *(__half2*)&sB[lm * 132 + n0] = __floats2half2_rn(v0, v1);
                    } else if (j == 2) {
                        *(__half2*)&g_Dh[(size_t)m * DIM + n0] = __floats2half2_rn(v0, v1);
                    } else {
                        const __half2 eh = __floats2half2_rn(v0, v1);
                        const __half2 bh = *(__half2*)&sB[lm * 132 + n0];
                        __half2 lo = __lows2half2(eh, bh);   // {e0, b0}
                        __half2 hi = __highs2half2(eh, bh);  // {e1, b1}
                        uint2 u;
                        u.x = *reinterpret_cast<unsigned*>(&lo);
                        u.y = *reinterpret_cast<unsigned*>(&hi);
                        *(uint2*)&g_EB[(size_t)m * 256 + 2 * n0] = u;
                    }
                }
            }
        }
    }
}

// ---------------- kernel 3: fused edge kernel ----------------
// e staged RAW fp32 in sE for the MMA; fp16 residual copy parked in sR (no 2nd global read).
// e_out computed in the gather epilogue (full e_ij = Ce + Dx[dst] + Ex[src]).
__global__ void __launch_bounds__(256, 4) edge_kernel(
    const float* __restrict__ e,
    const float* __restrict__ Cb,
    const void* __restrict__ eidx,
    const float* __restrict__ beg, const float* __restrict__ beb,
    const float* __restrict__ bem, const float* __restrict__ bev,
    float* __restrict__ e_out) {
    extern __shared__ unsigned smem[];
    unsigned* sE = smem;                        // raw fp32 e tile; aliased by sO after GEMM
    float* sO = (float*)smem;                   // fp32 Ce tile (overwrites sE)
    __half* sR = (__half*)(smem + 64 * 132);    // fp16 e residual tile

    const int tid = threadIdx.x;
    const size_t eBase = (size_t)blockIdx.x * 64;
    const uint2* Wf = g_Wf[4];

    // stage e tile: raw fp32 for MMA + fp16 residual copy
    for (int i = tid; i < 64 * 32; i += 256) {
        int row = i >> 5, c4 = (i & 31) << 2;
        float4 v = *(const float4*)&e[(eBase + row) * DIM + c4];
        float* p = (float*)&sE[row * 132 + c4];
        p[0] = v.x; p[1] = v.y; p[2] = v.z; p[3] = v.w;
        __half2 h01 = __floats2half2_rn(v.x, v.y);
        __half2 h23 = __floats2half2_rn(v.z, v.w);
        uint2 u;
        u.x = *reinterpret_cast<unsigned*>(&h01);
        u.y = *reinterpret_cast<unsigned*>(&h23);
        *(uint2*)&sR[row * 132 + c4] = u;
    }
    __syncthreads();

    const int lane = tid & 31, wid = tid >> 5;
    const int r = lane >> 2, c = lane & 3;
    const int mBase = (wid & 1) * 32;
    const int nBase = (wid >> 1) * 32;
    const int nb = (wid >> 1) * 4;

    float acc[2][4][4];
#pragma unroll
    for (int tj = 0; tj < 4; tj++) {
        int n0 = nBase + tj * 8 + c * 2;
        float bv0 = __ldg(&Cb[n0]), bv1 = __ldg(&Cb[n0 + 1]);
#pragma unroll
        for (int ti = 0; ti < 2; ti++) {
            acc[ti][tj][0] = bv0; acc[ti][tj][1] = bv1;
            acc[ti][tj][2] = bv0; acc[ti][tj][3] = bv1;
        }
    }

    gemm_tile(sE, Wf, acc, mBase, nb, r, c, lane);

    __syncthreads();  // all sE reads done -> safe to overwrite with sO
#pragma unroll
    for (int ti = 0; ti < 2; ti++) {
        int m = mBase + ti * 16 + r;
#pragma unroll
        for (int tj = 0; tj < 4; tj++) {
            int n0 = nBase + tj * 8 + c * 2;
            sO[m * 132 + n0]           = acc[ti][tj][0];
            sO[m * 132 + n0 + 1]       = acc[ti][tj][1];
            sO[(m + 8) * 132 + n0]     = acc[ti][tj][2];
            sO[(m + 8) * 132 + n0 + 1] = acc[ti][tj][3];
        }
    }
    __syncthreads();

    // ---- epilogue: warp w handles edges w*8..w*8+7, lane owns cols 4*lane..+3
    const int n = lane * 4;
    const float4 gm = *(const float4*)&beg[n];
    const float4 bt = *(const float4*)&beb[n];
    const float4 mn = *(const float4*)&bem[n];
    const float4 vr = *(const float4*)&bev[n];
    const float s0c = gm.x * rsqrtf(vr.x + 1e-5f);
    const float s1c = gm.y * rsqrtf(vr.y + 1e-5f);
    const float s2c = gm.z * rsqrtf(vr.z + 1e-5f);
    const float s3c = gm.w * rsqrtf(vr.w + 1e-5f);
    const float h0c = bt.x - mn.x * s0c;
    const float h1c = bt.y - mn.y * s1c;
    const float h2c = bt.z - mn.z * s2c;
    const float h3c = bt.w - mn.w * s3c;

    const int flag = g_i64;
    const long long* i64p = (const long long*)eidx;
    const int* i32p = (const int*)eidx;

    int srcs[8], dsts[8];
    if (flag) {
#pragma unroll
        for (int mi = 0; mi < 8; mi++) {
            const size_t ge = eBase + wid * 8 + mi;
            srcs[mi] = (int)__ldg(&i64p[ge]);
            dsts[mi] = (int)__ldg(&i64p[NE + ge]);
        }
    } else {
#pragma unroll
        for (int mi = 0; mi < 8; mi++) {
            const size_t ge = eBase + wid * 8 + mi;
            srcs[mi] = __ldg(&i32p[ge]);
            dsts[mi] = __ldg(&i32p[NE + ge]);
        }
    }

#pragma unroll
    for (int mi = 0; mi < 8; mi++) {
        const int m = wid * 8 + mi;
        const size_t ge = eBase + m;
        const int srcI = srcs[mi], dstI = dsts[mi];

        const uint4 ebu = __ldg((const uint4*)&g_EB[(size_t)srcI * 256 + 2 * n]);
        const uint2 dhu = __ldg((const uint2*)&g_Dh[(size_t)dstI * DIM + n]);

        const float2 eb0 = __half22float2(*(const __half2*)&ebu.x);  // {ex0, bx0}
        const float2 eb1 = __half22float2(*(const __half2*)&ebu.y);
        const float2 eb2 = __half22float2(*(const __half2*)&ebu.z);
        const float2 eb3 = __half22float2(*(const __half2*)&ebu.w);
        const float2 d01 = __half22float2(*(const __half2*)&dhu.x);
        const float2 d23 = __half22float2(*(const __half2*)&dhu.y);

        const float4 ce = *(const float4*)&sO[m * 132 + n];

        const float e0 = ce.x + d01.x + eb0.x;
        const float e1 = ce.y + d01.y + eb1.x;
        const float e2 = ce.z + d23.x + eb2.x;
        const float e3 = ce.w + d23.y + eb3.x;

        const float sg0 = sigmoidf_(e0);
        const float sg1 = sigmoidf_(e1);
        const float sg2 = sigmoidf_(e2);
        const float sg3 = sigmoidf_(e3);

        float* np = &g_num[(size_t)dstI * DIM + n];
        asm volatile("red.global.add.v4.f32 [%0], {%1,%2,%3,%4};"
                     :: "l"(np), "f"(sg0 * eb0.y), "f"(sg1 * eb1.y),
                        "f"(sg2 * eb2.y), "f"(sg3 * eb3.y)
                     : "memory");
        float* dp = &g_den[(size_t)dstI * DIM + n];
        asm volatile("red.global.add.v4.f32 [%0], {%1,%2,%3,%4};"
                     :: "l"(dp), "f"(sg0), "f"(sg1), "f"(sg2), "f"(sg3)
                     : "memory");

        // residual from smem (fp16 copy), no global re-read
        const uint2 ru = *(const uint2*)&sR[m * 132 + n];
        const float2 r01 = __half22float2(*(const __half2*)&ru.x);
        const float2 r23 = __half22float2(*(const __half2*)&ru.y);
        float4 o;
        o.x = r01.x + fmaxf(0.f, e0 * s0c + h0c);
        o.y = r01.y + fmaxf(0.f, e1 * s1c + h1c);
        o.z = r23.x + fmaxf(0.f, e2 * s2c + h2c);
        o.w = r23.y + fmaxf(0.f, e3 * s3c + h3c);
        asm volatile("st.global.cs.v4.f32 [%0], {%1,%2,%3,%4};"
                     :: "l"(&e_out[ge * DIM + n]),
                        "f"(o.x), "f"(o.y), "f"(o.z), "f"(o.w)
                     : "memory");
    }
}

// ---------------- kernel 4: node update ----------------
__global__ void update_kernel(const float* __restrict__ x,
                              const float* __restrict__ bxg, const float* __restrict__ bxb,
                              const float* __restrict__ bxm, const float* __restrict__ bxv,
                              float* __restrict__ x_out) {
    const size_t i = (size_t)blockIdx.x * 256 + threadIdx.x;
    const int c4 = ((int)i & 31) << 2;

    const float4 nu = ((const float4*)g_num)[i];
    const float4 de = ((const float4*)g_den)[i];
    const float4 ax = ((const float4*)g_Ax)[i];
    const float4 xv = ((const float4*)x)[i];

    const float4 gm = *(const float4*)&bxg[c4];
    const float4 bt = *(const float4*)&bxb[c4];
    const float4 mn = *(const float4*)&bxm[c4];
    const float4 vr = *(const float4*)&bxv[c4];

    const float s0 = gm.x * rsqrtf(vr.x + 1e-5f);
    const float s1 = gm.y * rsqrtf(vr.y + 1e-5f);
    const float s2 = gm.z * rsqrtf(vr.z + 1e-5f);
    const float s3 = gm.w * rsqrtf(vr.w + 1e-5f);
    const float h0 = bt.x - mn.x * s0;
    const float h1 = bt.y - mn.y * s1;
    const float h2 = bt.z - mn.z * s2;
    const float h3 = bt.w - mn.w * s3;

    const float v0 = ax.x + nu.x / (de.x + 1e-6f);
    const float v1 = ax.y + nu.y / (de.y + 1e-6f);
    const float v2 = ax.z + nu.z / (de.z + 1e-6f);
    const float v3 = ax.w + nu.w / (de.w + 1e-6f);

    float4 o;
    o.x = xv.x + fmaxf(0.f, v0 * s0 + h0);
    o.y = xv.y + fmaxf(0.f, v1 * s1 + h1);
    o.z = xv.z + fmaxf(0.f, v2 * s2 + h2);
    o.w = xv.w + fmaxf(0.f, v3 * s3 + h3);
    asm volatile("st.global.cs.v4.f32 [%0], {%1,%2,%3,%4};"
                 :: "l"(&((float4*)x_out)[i]),
                    "f"(o.x), "f"(o.y), "f"(o.z), "f"(o.w)
                 : "memory");
}

// ---------------- launch ----------------
extern "C" void kernel_launch(void* const* d_in, const int* in_sizes, int n_in,
                              void* d_out, int out_size) {
    const float* x  = (const float*)d_in[0];
    const float* e  = (const float*)d_in[1];
    const float* Aw = (const float*)d_in[2];
    const float* Ab = (const float*)d_in[3];
    const float* Bw = (const float*)d_in[4];
    const float* Bb = (const float*)d_in[5];
    const float* Cw = (const float*)d_in[6];
    const float* Cb = (const float*)d_in[7];
    const float* Dw = (const float*)d_in[8];
    const float* Db = (const float*)d_in[9];
    const float* Ew = (const float*)d_in[10];
    const float* Eb = (const float*)d_in[11];
    const float* bxg = (const float*)d_in[12];
    const float* bxb = (const float*)d_in[13];
    const float* bxm = (const float*)d_in[14];
    const float* bxv = (const float*)d_in[15];
    const float* beg = (const float*)d_in[16];
    const float* beb = (const float*)d_in[17];
    const float* bem = (const float*)d_in[18];
    const float* bev = (const float*)d_in[19];
    const void*  eidx = d_in[20];

    float* x_out = (float*)d_out;
    float* e_out = x_out + (size_t)NN * DIM;

    cudaFuncSetAttribute(node_gemm_kernel, cudaFuncAttributeMaxDynamicSharedMemorySize, SMEM_NODE);
    cudaFuncSetAttribute(edge_kernel, cudaFuncAttributeMaxDynamicSharedMemorySize, SMEM_EDGE);

    zero_kernel<<<6250, 256>>>();
    detect_kernel<<<1, 32>>>((const unsigned*)eidx);
    // weight order: 0:A 1:B 2:D 3:E 4:C
    prep_kernel<<<dim3(256, 5), 32>>>(Aw, Bw, Dw, Ew, Cw);
    node_gemm_kernel<<<dim3(782, 2), 256, SMEM_NODE>>>(x, Ab, Bb, Db, Eb);
    edge_kernel<<<10000, 256, SMEM_EDGE>>>(e, Cb, eidx, beg, beb, bem, bev, e_out);
    update_kernel<<<6250, 256>>>(x, bxg, bxb, bxm, bxv, x_out);
}

// round 9
// speedup vs baseline: 1.0359x; 1.0359x over previous
#include <cuda_runtime.h>
#include <cuda_fp16.h>
#include <cstdint>

#define NN 50000
#define NE 640000
#define DIM 128

// ---------------- scratch (device globals: allocation-free rule) ----------------
__device__ float  g_Ax[NN * DIM];            // A output, fp32
__device__ __half g_Bh[NN * DIM];            // B output, fp16
__device__ __half g_Dh[NN * DIM];            // D output, fp16
__device__ __half g_Eh[NN * DIM];            // E output, fp16
__device__ float  g_num[NN * DIM];
__device__ float  g_den[NN * DIM];
__device__ uint2  g_Wf[5][16 * 16 * 32];     // fragment-packed tf32 weights: A,B,D,E,C
__device__ int    g_i64;

// ---------------- helpers ----------------
__device__ __forceinline__ unsigned f2tf32(float f) {
    unsigned u;
    asm("cvt.rna.tf32.f32 %0, %1;" : "=r"(u) : "f"(f));
    return u;
}

__device__ __forceinline__ void mma_tf32(float c[4], const unsigned a[4],
                                         unsigned b0, unsigned b1) {
    asm volatile(
        "mma.sync.aligned.m16n8k8.row.col.f32.tf32.tf32.f32 "
        "{%0,%1,%2,%3}, {%4,%5,%6,%7}, {%8,%9}, {%0,%1,%2,%3};"
        : "+f"(c[0]), "+f"(c[1]), "+f"(c[2]), "+f"(c[3])
        : "r"(a[0]), "r"(a[1]), "r"(a[2]), "r"(a[3]), "r"(b0), "r"(b1));
}

__device__ __forceinline__ float sigmoidf_(float v) {
    return 1.0f / (1.0f + __expf(-v));
}

// 64x128x128 GEMM core. sA: [64][132] 32-bit operands in smem (tf32 or raw fp32 bits).
__device__ __forceinline__ void gemm_tile(const unsigned* sA, const uint2* __restrict__ Wf,
                                          float acc[2][4][4], int mBase, int nb,
                                          int r, int c, int lane) {
#pragma unroll 4
    for (int ks = 0; ks < 16; ks++) {
        uint2 b[4];
#pragma unroll
        for (int tj = 0; tj < 4; tj++)
            b[tj] = __ldg(&Wf[(ks * 16 + nb + tj) * 32 + lane]);
        unsigned a[2][4];
#pragma unroll
        for (int ti = 0; ti < 2; ti++) {
            const unsigned* ap = &sA[(mBase + ti * 16 + r) * 132 + ks * 8 + c];
            a[ti][0] = ap[0];
            a[ti][1] = ap[8 * 132];
            a[ti][2] = ap[4];
            a[ti][3] = ap[8 * 132 + 4];
        }
#pragma unroll
        for (int ti = 0; ti < 2; ti++)
#pragma unroll
            for (int tj = 0; tj < 4; tj++)
                mma_tf32(acc[ti][tj], a[ti], b[tj].x, b[tj].y);
    }
}

static const int SMEM_TILE = 64 * 132 * 4;  // 33792 B (node + edge kernels)

// ---------------- kernel 0: zero num/den ----------------
__global__ void zero_kernel() {
    size_t i = (size_t)blockIdx.x * blockDim.x + threadIdx.x;
    float4 z = make_float4(0.f, 0.f, 0.f, 0.f);
    ((float4*)g_num)[i] = z;
    ((float4*)g_den)[i] = z;
}

// ---------------- kernel 1: detect edge_index dtype ----------------
__global__ void detect_kernel(const unsigned* __restrict__ w) {
    unsigned acc = 0;
    for (int i = threadIdx.x; i < 1024; i += 32) acc |= w[2 * i + 1];
#pragma unroll
    for (int o = 16; o; o >>= 1) acc |= __shfl_xor_sync(0xffffffffu, acc, o);
    if (threadIdx.x == 0) g_i64 = (acc == 0) ? 1 : 0;
}

// ---------------- kernel 1b: pack weights into fragment layout (tf32) ----------------
__global__ void prep_kernel(const float* __restrict__ W0, const float* __restrict__ W1,
                            const float* __restrict__ W2, const float* __restrict__ W3,
                            const float* __restrict__ W4) {
    const float* Ws[5] = {W0, W1, W2, W3, W4};
    const int lane = threadIdx.x;
    const int g = blockIdx.x;      // ks*16+ng
    const int mat = blockIdx.y;
    const int ks = g >> 4, ng = g & 15;
    const int r = lane >> 2, c = lane & 3;
    const float* W = Ws[mat];
    const int n = ng * 8 + r;
    const int k = ks * 8 + c;
    uint2 v;
    v.x = f2tf32(W[n * DIM + k]);
    v.y = f2tf32(W[n * DIM + k + 4]);
    g_Wf[mat][g * 32 + lane] = v;
}

// ---------------- kernel 2: node GEMMs, one j per block (R2 geometry, small smem) ----------------
// j = blockIdx.y: 0->g_Ax fp32, 1->g_Bh half2, 2->g_Dh half2, 3->g_Eh half2
__global__ void __launch_bounds__(256, 4) node_gemm_kernel(
    const float* __restrict__ x,
    const float* __restrict__ b0, const float* __restrict__ b1,
    const float* __restrict__ b2, const float* __restrict__ b3) {
    extern __shared__ unsigned smem[];
    unsigned* sX = smem;  // 64*132 words (tf32 x tile)

    const int tid = threadIdx.x;
    const int m0 = blockIdx.x * 64;
    const int j = blockIdx.y;

    const float* bias = (j == 0) ? b0 : (j == 1) ? b1 : (j == 2) ? b2 : b3;
    const uint2* Wf = g_Wf[j];

    for (int i = tid; i < 64 * 32; i += 256) {
        int row = i >> 5, c4 = (i & 31) << 2;
        float4 v = make_float4(0.f, 0.f, 0.f, 0.f);
        if (m0 + row < NN) v = *(const float4*)&x[(size_t)(m0 + row) * DIM + c4];
        unsigned* p = &sX[row * 132 + c4];
        p[0] = f2tf32(v.x); p[1] = f2tf32(v.y); p[2] = f2tf32(v.z); p[3] = f2tf32(v.w);
    }
    __syncthreads();

    const int lane = tid & 31, wid = tid >> 5;
    const int r = lane >> 2, c = lane & 3;
    const int mBase = (wid & 1) * 32;
    const int nBase = (wid >> 1) * 32;
    const int nb = (wid >> 1) * 4;

    float acc[2][4][4];
#pragma unroll
    for (int tj = 0; tj < 4; tj++) {
        int n0 = nBase + tj * 8 + c * 2;
        float bv0 = __ldg(&bias[n0]), bv1 = __ldg(&bias[n0 + 1]);
#pragma unroll
        for (int ti = 0; ti < 2; ti++) {
            acc[ti][tj][0] = bv0; acc[ti][tj][1] = bv1;
            acc[ti][tj][2] = bv0; acc[ti][tj][3] = bv1;
        }
    }

    gemm_tile(sX, Wf, acc, mBase, nb, r, c, lane);

    __half* outH = (j == 1) ? g_Bh : (j == 2) ? g_Dh : g_Eh;
#pragma unroll
    for (int ti = 0; ti < 2; ti++) {
#pragma unroll
        for (int half_i = 0; half_i < 2; half_i++) {
            const int m = m0 + mBase + ti * 16 + r + half_i * 8;
            if (m >= NN) continue;
#pragma unroll
            for (int tj = 0; tj < 4; tj++) {
                const int n0 = nBase + tj * 8 + c * 2;
                const float v0 = acc[ti][tj][half_i * 2];
                const float v1 = acc[ti][tj][half_i * 2 + 1];
                if (j == 0) {
                    *(float2*)&g_Ax[(size_t)m * DIM + n0] = make_float2(v0, v1);
                } else {
                    *(__half2*)&outH[(size_t)m * DIM + n0] = __floats2half2_rn(v0, v1);
                }
            }
        }
    }
}

// ---------------- kernel 3: fused edge kernel (R7 structure, small smem) ----------------
// e staged RAW fp32 in sE (mma truncates); e_out in gather epilogue with global .cs residual re-read.
__global__ void __launch_bounds__(256, 4) edge_kernel(
    const float* __restrict__ e,
    const float* __restrict__ Cb,
    const void* __restrict__ eidx,
    const float* __restrict__ beg, const float* __restrict__ beb,
    const float* __restrict__ bem, const float* __restrict__ bev,
    float* __restrict__ e_out) {
    extern __shared__ unsigned smem[];
    unsigned* sE = smem;       // raw fp32 e tile; aliased by sO after GEMM
    float* sO = (float*)smem;  // fp32 Ce tile (overwrites sE)

    const int tid = threadIdx.x;
    const size_t eBase = (size_t)blockIdx.x * 64;
    const uint2* Wf = g_Wf[4];

    for (int i = tid; i < 64 * 32; i += 256) {
        int row = i >> 5, c4 = (i & 31) << 2;
        float4 v = *(const float4*)&e[(eBase + row) * DIM + c4];
        float* p = (float*)&sE[row * 132 + c4];
        p[0] = v.x; p[1] = v.y; p[2] = v.z; p[3] = v.w;
    }
    __syncthreads();

    const int lane = tid & 31, wid = tid >> 5;
    const int r = lane >> 2, c = lane & 3;
    const int mBase = (wid & 1) * 32;
    const int nBase = (wid >> 1) * 32;
    const int nb = (wid >> 1) * 4;

    float acc[2][4][4];
#pragma unroll
    for (int tj = 0; tj < 4; tj++) {
        int n0 = nBase + tj * 8 + c * 2;
        float bv0 = __ldg(&Cb[n0]), bv1 = __ldg(&Cb[n0 + 1]);
#pragma unroll
        for (int ti = 0; ti < 2; ti++) {
            acc[ti][tj][0] = bv0; acc[ti][tj][1] = bv1;
            acc[ti][tj][2] = bv0; acc[ti][tj][3] = bv1;
        }
    }

    gemm_tile(sE, Wf, acc, mBase, nb, r, c, lane);

    __syncthreads();  // all sE reads done -> safe to overwrite with sO
#pragma unroll
    for (int ti = 0; ti < 2; ti++) {
        int m = mBase + ti * 16 + r;
#pragma unroll
        for (int tj = 0; tj < 4; tj++) {
            int n0 = nBase + tj * 8 + c * 2;
            sO[m * 132 + n0]           = acc[ti][tj][0];
            sO[m * 132 + n0 + 1]       = acc[ti][tj][1];
            sO[(m + 8) * 132 + n0]     = acc[ti][tj][2];
            sO[(m + 8) * 132 + n0 + 1] = acc[ti][tj][3];
        }
    }
    __syncthreads();

    // ---- epilogue: warp w handles edges w*8..w*8+7, lane owns cols 4*lane..+3
    const int n = lane * 4;
    const float4 gm = *(const float4*)&beg[n];
    const float4 bt = *(const float4*)&beb[n];
    const float4 mn = *(const float4*)&bem[n];
    const float4 vr = *(const float4*)&bev[n];
    const float s0c = gm.x * rsqrtf(vr.x + 1e-5f);
    const float s1c = gm.y * rsqrtf(vr.y + 1e-5f);
    const float s2c = gm.z * rsqrtf(vr.z + 1e-5f);
    const float s3c = gm.w * rsqrtf(vr.w + 1e-5f);
    const float h0c = bt.x - mn.x * s0c;
    const float h1c = bt.y - mn.y * s1c;
    const float h2c = bt.z - mn.z * s2c;
    const float h3c = bt.w - mn.w * s3c;

    const int flag = g_i64;
    const long long* i64p = (const long long*)eidx;
    const int* i32p = (const int*)eidx;

    int srcs[8], dsts[8];
    if (flag) {
#pragma unroll
        for (int mi = 0; mi < 8; mi++) {
            const size_t ge = eBase + wid * 8 + mi;
            srcs[mi] = (int)__ldg(&i64p[ge]);
            dsts[mi] = (int)__ldg(&i64p[NE + ge]);
        }
    } else {
#pragma unroll
        for (int mi = 0; mi < 8; mi++) {
            const size_t ge = eBase + wid * 8 + mi;
            srcs[mi] = __ldg(&i32p[ge]);
            dsts[mi] = __ldg(&i32p[NE + ge]);
        }
    }

#pragma unroll
    for (int mi = 0; mi < 8; mi++) {
        const int m = wid * 8 + mi;
        const size_t ge = eBase + m;
        const int srcI = srcs[mi], dstI = dsts[mi];

        const uint2 exu = __ldg((const uint2*)&g_Eh[(size_t)srcI * DIM + n]);
        const uint2 bxu = __ldg((const uint2*)&g_Bh[(size_t)srcI * DIM + n]);
        const uint2 dhu = __ldg((const uint2*)&g_Dh[(size_t)dstI * DIM + n]);

        const float2 ex01 = __half22float2(*(const __half2*)&exu.x);
        const float2 ex23 = __half22float2(*(const __half2*)&exu.y);
        const float2 bx01 = __half22float2(*(const __half2*)&bxu.x);
        const float2 bx23 = __half22float2(*(const __half2*)&bxu.y);
        const float2 d01  = __half22float2(*(const __half2*)&dhu.x);
        const float2 d23  = __half22float2(*(const __half2*)&dhu.y);

        const float4 ce = *(const float4*)&sO[m * 132 + n];

        const float e0 = ce.x + d01.x + ex01.x;
        const float e1 = ce.y + d01.y + ex01.y;
        const float e2 = ce.z + d23.x + ex23.x;
        const float e3 = ce.w + d23.y + ex23.y;

        const float sg0 = sigmoidf_(e0);
        const float sg1 = sigmoidf_(e1);
        const float sg2 = sigmoidf_(e2);
        const float sg3 = sigmoidf_(e3);

        float* np = &g_num[(size_t)dstI * DIM + n];
        asm volatile("red.global.add.v4.f32 [%0], {%1,%2,%3,%4};"
                     :: "l"(np), "f"(sg0 * bx01.x), "f"(sg1 * bx01.y),
                        "f"(sg2 * bx23.x), "f"(sg3 * bx23.y)
                     : "memory");
        float* dp = &g_den[(size_t)dstI * DIM + n];
        asm volatile("red.global.add.v4.f32 [%0], {%1,%2,%3,%4};"
                     :: "l"(dp), "f"(sg0), "f"(sg1), "f"(sg2), "f"(sg3)
                     : "memory");

        // residual re-read: mostly L2-hit (staged moments ago); .cs = evict-first
        float4 ev;
        asm volatile("ld.global.cs.v4.f32 {%0,%1,%2,%3}, [%4];"
                     : "=f"(ev.x), "=f"(ev.y), "=f"(ev.z), "=f"(ev.w)
                     : "l"(&e[ge * DIM + n]));
        float4 o;
        o.x = ev.x + fmaxf(0.f, e0 * s0c + h0c);
        o.y = ev.y + fmaxf(0.f, e1 * s1c + h1c);
        o.z = ev.z + fmaxf(0.f, e2 * s2c + h2c);
        o.w = ev.w + fmaxf(0.f, e3 * s3c + h3c);
        asm volatile("st.global.cs.v4.f32 [%0], {%1,%2,%3,%4};"
                     :: "l"(&e_out[ge * DIM + n]),
                        "f"(o.x), "f"(o.y), "f"(o.z), "f"(o.w)
                     : "memory");
    }
}

// ---------------- kernel 4: node update ----------------
__global__ void update_kernel(const float* __restrict__ x,
                              const float* __restrict__ bxg, const float* __restrict__ bxb,
                              const float* __restrict__ bxm, const float* __restrict__ bxv,
                              float* __restrict__ x_out) {
    const size_t i = (size_t)blockIdx.x * 256 + threadIdx.x;
    const int c4 = ((int)i & 31) << 2;

    const float4 nu = ((const float4*)g_num)[i];
    const float4 de = ((const float4*)g_den)[i];
    const float4 ax = ((const float4*)g_Ax)[i];
    const float4 xv = ((const float4*)x)[i];

    const float4 gm = *(const float4*)&bxg[c4];
    const float4 bt = *(const float4*)&bxb[c4];
    const float4 mn = *(const float4*)&bxm[c4];
    const float4 vr = *(const float4*)&bxv[c4];

    const float s0 = gm.x * rsqrtf(vr.x + 1e-5f);
    const float s1 = gm.y * rsqrtf(vr.y + 1e-5f);
    const float s2 = gm.z * rsqrtf(vr.z + 1e-5f);
    const float s3 = gm.w * rsqrtf(vr.w + 1e-5f);
    const float h0 = bt.x - mn.x * s0;
    const float h1 = bt.y - mn.y * s1;
    const float h2 = bt.z - mn.z * s2;
    const float h3 = bt.w - mn.w * s3;

    const float v0 = ax.x + nu.x / (de.x + 1e-6f);
    const float v1 = ax.y + nu.y / (de.y + 1e-6f);
    const float v2 = ax.z + nu.z / (de.z + 1e-6f);
    const float v3 = ax.w + nu.w / (de.w + 1e-6f);

    float4 o;
    o.x = xv.x + fmaxf(0.f, v0 * s0 + h0);
    o.y = xv.y + fmaxf(0.f, v1 * s1 + h1);
    o.z = xv.z + fmaxf(0.f, v2 * s2 + h2);
    o.w = xv.w + fmaxf(0.f, v3 * s3 + h3);
    asm volatile("st.global.cs.v4.f32 [%0], {%1,%2,%3,%4};"
                 :: "l"(&((float4*)x_out)[i]),
                    "f"(o.x), "f"(o.y), "f"(o.z), "f"(o.w)
                 : "memory");
}

// ---------------- launch ----------------
extern "C" void kernel_launch(void* const* d_in, const int* in_sizes, int n_in,
                              void* d_out, int out_size) {
    const float* x  = (const float*)d_in[0];
    const float* e  = (const float*)d_in[1];
    const float* Aw = (const float*)d_in[2];
    const float* Ab = (const float*)d_in[3];
    const float* Bw = (const float*)d_in[4];
    const float* Bb = (const float*)d_in[5];
    const float* Cw = (const float*)d_in[6];
    const float* Cb = (const float*)d_in[7];
    const float* Dw = (const float*)d_in[8];
    const float* Db = (const float*)d_in[9];
    const float* Ew = (const float*)d_in[10];
    const float* Eb = (const float*)d_in[11];
    const float* bxg = (const float*)d_in[12];
    const float* bxb = (const float*)d_in[13];
    const float* bxm = (const float*)d_in[14];
    const float* bxv = (const float*)d_in[15];
    const float* beg = (const float*)d_in[16];
    const float* beb = (const float*)d_in[17];
    const float* bem = (const float*)d_in[18];
    const float* bev = (const float*)d_in[19];
    const void*  eidx = d_in[20];

    float* x_out = (float*)d_out;
    float* e_out = x_out + (size_t)NN * DIM;

    zero_kernel<<<6250, 256>>>();
    detect_kernel<<<1, 32>>>((const unsigned*)eidx);
    // weight order: 0:A 1:B 2:D 3:E 4:C
    prep_kernel<<<dim3(256, 5), 32>>>(Aw, Bw, Dw, Ew, Cw);
    // node j mapping: blockIdx.y 0->A, 1->B(g_Bh), 2->D(g_Dh), 3->E(g_Eh)
    node_gemm_kernel<<<dim3(782, 4), 256, SMEM_TILE>>>(x, Ab, Bb, Db, Eb);
    edge_kernel<<<10000, 256, SMEM_TILE>>>(e, Cb, eidx, beg, beb, bem, bev, e_out);
    update_kernel<<<6250, 256>>>(x, bxg, bxb, bxm, bxv, x_out);
}

// round 10
// speedup vs baseline: 1.1283x; 1.0893x over previous
#include <cuda_runtime.h>
#include <cuda_fp16.h>
#include <cstdint>

#define NN 50000
#define NE 640000
#define DIM 128

// ---------------- scratch (device globals: allocation-free rule) ----------------
__device__ float  g_Ax[NN * DIM];            // A output, fp32
__device__ __half g_Bh[NN * DIM];            // B output, fp16
__device__ __half g_Dh[NN * DIM];            // D output, fp16
__device__ __half g_Eh[NN * DIM];            // E output, fp16
__device__ __half g_numh[NN * DIM];          // fp16 atomic accumulators
__device__ __half g_denh[NN * DIM];
__device__ uint2  g_Wf[5][16 * 16 * 32];     // fragment-packed tf32 weights: A,B,D,E,C
__device__ int    g_i64;

// ---------------- helpers ----------------
__device__ __forceinline__ unsigned f2tf32(float f) {
    unsigned u;
    asm("cvt.rna.tf32.f32 %0, %1;" : "=r"(u) : "f"(f));
    return u;
}

__device__ __forceinline__ void mma_tf32(float c[4], const unsigned a[4],
                                         unsigned b0, unsigned b1) {
    asm volatile(
        "mma.sync.aligned.m16n8k8.row.col.f32.tf32.tf32.f32 "
        "{%0,%1,%2,%3}, {%4,%5,%6,%7}, {%8,%9}, {%0,%1,%2,%3};"
        : "+f"(c[0]), "+f"(c[1]), "+f"(c[2]), "+f"(c[3])
        : "r"(a[0]), "r"(a[1]), "r"(a[2]), "r"(a[3]), "r"(b0), "r"(b1));
}

__device__ __forceinline__ float sigmoidf_(float v) {
    return 1.0f / (1.0f + __expf(-v));
}

__device__ __forceinline__ unsigned pack_h2(float a, float b) {
    __half2 h = __floats2half2_rn(a, b);
    return *reinterpret_cast<unsigned*>(&h);
}

// 64x128x128 GEMM core. sA: [64][132] 32-bit operands in smem (tf32 or raw fp32 bits).
__device__ __forceinline__ void gemm_tile(const unsigned* sA, const uint2* __restrict__ Wf,
                                          float acc[2][4][4], int mBase, int nb,
                                          int r, int c, int lane) {
#pragma unroll 4
    for (int ks = 0; ks < 16; ks++) {
        uint2 b[4];
#pragma unroll
        for (int tj = 0; tj < 4; tj++)
            b[tj] = __ldg(&Wf[(ks * 16 + nb + tj) * 32 + lane]);
        unsigned a[2][4];
#pragma unroll
        for (int ti = 0; ti < 2; ti++) {
            const unsigned* ap = &sA[(mBase + ti * 16 + r) * 132 + ks * 8 + c];
            a[ti][0] = ap[0];
            a[ti][1] = ap[8 * 132];
            a[ti][2] = ap[4];
            a[ti][3] = ap[8 * 132 + 4];
        }
#pragma unroll
        for (int ti = 0; ti < 2; ti++)
#pragma unroll
            for (int tj = 0; tj < 4; tj++)
                mma_tf32(acc[ti][tj], a[ti], b[tj].x, b[tj].y);
    }
}

static const int SMEM_TILE = 64 * 132 * 4;  // 33792 B (node + edge kernels)

// ---------------- kernel 0: zero num/den (fp16) + detect edge_index dtype ----------------
// merged so edge_kernel lands in ncu's captured launch slot
__global__ void zero_detect_kernel(const unsigned* __restrict__ w) {
    const size_t i = (size_t)blockIdx.x * 256 + threadIdx.x;  // float4 index (8 halves)
    float4 z = make_float4(0.f, 0.f, 0.f, 0.f);
    ((float4*)g_numh)[i] = z;
    ((float4*)g_denh)[i] = z;
    if (blockIdx.x == 0 && threadIdx.x < 32) {
        unsigned acc = 0;
        for (int k = threadIdx.x; k < 1024; k += 32) acc |= w[2 * k + 1];
#pragma unroll
        for (int o = 16; o; o >>= 1) acc |= __shfl_xor_sync(0xffffffffu, acc, o);
        if (threadIdx.x == 0) g_i64 = (acc == 0) ? 1 : 0;
    }
}

// ---------------- kernel 1: pack weights into fragment layout (tf32) ----------------
__global__ void prep_kernel(const float* __restrict__ W0, const float* __restrict__ W1,
                            const float* __restrict__ W2, const float* __restrict__ W3,
                            const float* __restrict__ W4) {
    const float* Ws[5] = {W0, W1, W2, W3, W4};
    const int lane = threadIdx.x;
    const int g = blockIdx.x;      // ks*16+ng
    const int mat = blockIdx.y;
    const int ks = g >> 4, ng = g & 15;
    const int r = lane >> 2, c = lane & 3;
    const float* W = Ws[mat];
    const int n = ng * 8 + r;
    const int k = ks * 8 + c;
    uint2 v;
    v.x = f2tf32(W[n * DIM + k]);
    v.y = f2tf32(W[n * DIM + k + 4]);
    g_Wf[mat][g * 32 + lane] = v;
}

// ---------------- kernel 2: node GEMMs, one j per block ----------------
// j = blockIdx.y: 0->g_Ax fp32, 1->g_Bh half2, 2->g_Dh half2, 3->g_Eh half2
__global__ void __launch_bounds__(256, 4) node_gemm_kernel(
    const float* __restrict__ x,
    const float* __restrict__ b0, const float* __restrict__ b1,
    const float* __restrict__ b2, const float* __restrict__ b3) {
    extern __shared__ unsigned smem[];
    unsigned* sX = smem;  // 64*132 words (tf32 x tile)

    const int tid = threadIdx.x;
    const int m0 = blockIdx.x * 64;
    const int j = blockIdx.y;

    const float* bias = (j == 0) ? b0 : (j == 1) ? b1 : (j == 2) ? b2 : b3;
    const uint2* Wf = g_Wf[j];

    for (int i = tid; i < 64 * 32; i += 256) {
        int row = i >> 5, c4 = (i & 31) << 2;
        float4 v = make_float4(0.f, 0.f, 0.f, 0.f);
        if (m0 + row < NN) v = *(const float4*)&x[(size_t)(m0 + row) * DIM + c4];
        unsigned* p = &sX[row * 132 + c4];
        p[0] = f2tf32(v.x); p[1] = f2tf32(v.y); p[2] = f2tf32(v.z); p[3] = f2tf32(v.w);
    }
    __syncthreads();

    const int lane = tid & 31, wid = tid >> 5;
    const int r = lane >> 2, c = lane & 3;
    const int mBase = (wid & 1) * 32;
    const int nBase = (wid >> 1) * 32;
    const int nb = (wid >> 1) * 4;

    float acc[2][4][4];
#pragma unroll
    for (int tj = 0; tj < 4; tj++) {
        int n0 = nBase + tj * 8 + c * 2;
        float bv0 = __ldg(&bias[n0]), bv1 = __ldg(&bias[n0 + 1]);
#pragma unroll
        for (int ti = 0; ti < 2; ti++) {
            acc[ti][tj][0] = bv0; acc[ti][tj][1] = bv1;
            acc[ti][tj][2] = bv0; acc[ti][tj][3] = bv1;
        }
    }

    gemm_tile(sX, Wf, acc, mBase, nb, r, c, lane);

    __half* outH = (j == 1) ? g_Bh : (j == 2) ? g_Dh : g_Eh;
#pragma unroll
    for (int ti = 0; ti < 2; ti++) {
#pragma unroll
        for (int half_i = 0; half_i < 2; half_i++) {
            const int m = m0 + mBase + ti * 16 + r + half_i * 8;
            if (m >= NN) continue;
#pragma unroll
            for (int tj = 0; tj < 4; tj++) {
                const int n0 = nBase + tj * 8 + c * 2;
                const float v0 = acc[ti][tj][half_i * 2];
                const float v1 = acc[ti][tj][half_i * 2 + 1];
                if (j == 0) {
                    *(float2*)&g_Ax[(size_t)m * DIM + n0] = make_float2(v0, v1);
                } else {
                    *(__half2*)&outH[(size_t)m * DIM + n0] = __floats2half2_rn(v0, v1);
                }
            }
        }
    }
}

// ---------------- kernel 3: fused edge kernel ----------------
// e staged RAW fp32 in sE (mma truncates); e_out in gather epilogue; fp16 v2.f16x2 reds.
__global__ void __launch_bounds__(256, 4) edge_kernel(
    const float* __restrict__ e,
    const float* __restrict__ Cb,
    const void* __restrict__ eidx,
    const float* __restrict__ beg, const float* __restrict__ beb,
    const float* __restrict__ bem, const float* __restrict__ bev,
    float* __restrict__ e_out) {
    extern __shared__ unsigned smem[];
    unsigned* sE = smem;       // raw fp32 e tile; aliased by sO after GEMM
    float* sO = (float*)smem;  // fp32 Ce tile (overwrites sE)

    const int tid = threadIdx.x;
    const size_t eBase = (size_t)blockIdx.x * 64;
    const uint2* Wf = g_Wf[4];

    for (int i = tid; i < 64 * 32; i += 256) {
        int row = i >> 5, c4 = (i & 31) << 2;
        float4 v = *(const float4*)&e[(eBase + row) * DIM + c4];
        float* p = (float*)&sE[row * 132 + c4];
        p[0] = v.x; p[1] = v.y; p[2] = v.z; p[3] = v.w;
    }
    __syncthreads();

    const int lane = tid & 31, wid = tid >> 5;
    const int r = lane >> 2, c = lane & 3;
    const int mBase = (wid & 1) * 32;
    const int nBase = (wid >> 1) * 32;
    const int nb = (wid >> 1) * 4;

    float acc[2][4][4];
#pragma unroll
    for (int tj = 0; tj < 4; tj++) {
        int n0 = nBase + tj * 8 + c * 2;
        float bv0 = __ldg(&Cb[n0]), bv1 = __ldg(&Cb[n0 + 1]);
#pragma unroll
        for (int ti = 0; ti < 2; ti++) {
            acc[ti][tj][0] = bv0; acc[ti][tj][1] = bv1;
            acc[ti][tj][2] = bv0; acc[ti][tj][3] = bv1;
        }
    }

    gemm_tile(sE, Wf, acc, mBase, nb, r, c, lane);

    __syncthreads();  // all sE reads done -> safe to overwrite with sO
#pragma unroll
    for (int ti = 0; ti < 2; ti++) {
        int m = mBase + ti * 16 + r;
#pragma unroll
        for (int tj = 0; tj < 4; tj++) {
            int n0 = nBase + tj * 8 + c * 2;
            sO[m * 132 + n0]           = acc[ti][tj][0];
            sO[m * 132 + n0 + 1]       = acc[ti][tj][1];
            sO[(m + 8) * 132 + n0]     = acc[ti][tj][2];
            sO[(m + 8) * 132 + n0 + 1] = acc[ti][tj][3];
        }
    }
    __syncthreads();

    // ---- epilogue: warp w handles edges w*8..w*8+7, lane owns cols 4*lane..+3
    const int n = lane * 4;
    const float4 gm = *(const float4*)&beg[n];
    const float4 bt = *(const float4*)&beb[n];
    const float4 mn = *(const float4*)&bem[n];
    const float4 vr = *(const float4*)&bev[n];
    const float s0c = gm.x * rsqrtf(vr.x + 1e-5f);
    const float s1c = gm.y * rsqrtf(vr.y + 1e-5f);
    const float s2c = gm.z * rsqrtf(vr.z + 1e-5f);
    const float s3c = gm.w * rsqrtf(vr.w + 1e-5f);
    const float h0c = bt.x - mn.x * s0c;
    const float h1c = bt.y - mn.y * s1c;
    const float h2c = bt.z - mn.z * s2c;
    const float h3c = bt.w - mn.w * s3c;

    const int flag = g_i64;
    const long long* i64p = (const long long*)eidx;
    const int* i32p = (const int*)eidx;

    int srcs[8], dsts[8];
    if (flag) {
#pragma unroll
        for (int mi = 0; mi < 8; mi++) {
            const size_t ge = eBase + wid * 8 + mi;
            srcs[mi] = (int)__ldg(&i64p[ge]);
            dsts[mi] = (int)__ldg(&i64p[NE + ge]);
        }
    } else {
#pragma unroll
        for (int mi = 0; mi < 8; mi++) {
            const size_t ge = eBase + wid * 8 + mi;
            srcs[mi] = __ldg(&i32p[ge]);
            dsts[mi] = __ldg(&i32p[NE + ge]);
        }
    }

#pragma unroll
    for (int mi = 0; mi < 8; mi++) {
        const int m = wid * 8 + mi;
        const size_t ge = eBase + m;
        const int srcI = srcs[mi], dstI = dsts[mi];

        const uint2 exu = __ldg((const uint2*)&g_Eh[(size_t)srcI * DIM + n]);
        const uint2 bxu = __ldg((const uint2*)&g_Bh[(size_t)srcI * DIM + n]);
        const uint2 dhu = __ldg((const uint2*)&g_Dh[(size_t)dstI * DIM + n]);

        const float2 ex01 = __half22float2(*(const __half2*)&exu.x);
        const float2 ex23 = __half22float2(*(const __half2*)&exu.y);
        const float2 bx01 = __half22float2(*(const __half2*)&bxu.x);
        const float2 bx23 = __half22float2(*(const __half2*)&bxu.y);
        const float2 d01  = __half22float2(*(const __half2*)&dhu.x);
        const float2 d23  = __half22float2(*(const __half2*)&dhu.y);

        const float4 ce = *(const float4*)&sO[m * 132 + n];

        const float e0 = ce.x + d01.x + ex01.x;
        const float e1 = ce.y + d01.y + ex01.y;
        const float e2 = ce.z + d23.x + ex23.x;
        const float e3 = ce.w + d23.y + ex23.y;

        const float sg0 = sigmoidf_(e0);
        const float sg1 = sigmoidf_(e1);
        const float sg2 = sigmoidf_(e2);
        const float sg3 = sigmoidf_(e3);

        // fp16 atomics: half the L2 atomic traffic of v4.f32
        const unsigned nu0 = pack_h2(sg0 * bx01.x, sg1 * bx01.y);
        const unsigned nu1 = pack_h2(sg2 * bx23.x, sg3 * bx23.y);
        const unsigned de0 = pack_h2(sg0, sg1);
        const unsigned de1 = pack_h2(sg2, sg3);

        __half* np = &g_numh[(size_t)dstI * DIM + n];
        asm volatile("red.global.add.noftz.v2.f16x2 [%0], {%1,%2};"
                     :: "l"(np), "r"(nu0), "r"(nu1) : "memory");
        __half* dp = &g_denh[(size_t)dstI * DIM + n];
        asm volatile("red.global.add.noftz.v2.f16x2 [%0], {%1,%2};"
                     :: "l"(dp), "r"(de0), "r"(de1) : "memory");

        // residual re-read: mostly L2-hit (staged moments ago); .cs = evict-first
        float4 ev;
        asm volatile("ld.global.cs.v4.f32 {%0,%1,%2,%3}, [%4];"
                     : "=f"(ev.x), "=f"(ev.y), "=f"(ev.z), "=f"(ev.w)
                     : "l"(&e[ge * DIM + n]));
        float4 o;
        o.x = ev.x + fmaxf(0.f, e0 * s0c + h0c);
        o.y = ev.y + fmaxf(0.f, e1 * s1c + h1c);
        o.z = ev.z + fmaxf(0.f, e2 * s2c + h2c);
        o.w = ev.w + fmaxf(0.f, e3 * s3c + h3c);
        asm volatile("st.global.cs.v4.f32 [%0], {%1,%2,%3,%4};"
                     :: "l"(&e_out[ge * DIM + n]),
                        "f"(o.x), "f"(o.y), "f"(o.z), "f"(o.w)
                     : "memory");
    }
}

// ---------------- kernel 4: node update ----------------
__global__ void update_kernel(const float* __restrict__ x,
                              const float* __restrict__ bxg, const float* __restrict__ bxb,
                              const float* __restrict__ bxm, const float* __restrict__ bxv,
                              float* __restrict__ x_out) {
    const size_t i = (size_t)blockIdx.x * 256 + threadIdx.x;  // float4 / 4-col index
    const int c4 = ((int)i & 31) << 2;

    const uint2 nuu = ((const uint2*)g_numh)[i];
    const uint2 deu = ((const uint2*)g_denh)[i];
    const float2 nu01 = __half22float2(*(const __half2*)&nuu.x);
    const float2 nu23 = __half22float2(*(const __half2*)&nuu.y);
    const float2 de01 = __half22float2(*(const __half2*)&deu.x);
    const float2 de23 = __half22float2(*(const __half2*)&deu.y);

    const float4 ax = ((const float4*)g_Ax)[i];
    const float4 xv = ((const float4*)x)[i];

    const float4 gm = *(const float4*)&bxg[c4];
    const float4 bt = *(const float4*)&bxb[c4];
    const float4 mn = *(const float4*)&bxm[c4];
    const float4 vr = *(const float4*)&bxv[c4];

    const float s0 = gm.x * rsqrtf(vr.x + 1e-5f);
    const float s1 = gm.y * rsqrtf(vr.y + 1e-5f);
    const float s2 = gm.z * rsqrtf(vr.z + 1e-5f);
    const float s3 = gm.w * rsqrtf(vr.w + 1e-5f);
    const float h0 = bt.x - mn.x * s0;
    const float h1 = bt.y - mn.y * s1;
    const float h2 = bt.z - mn.z * s2;
    const float h3 = bt.w - mn.w * s3;

    const float v0 = ax.x + nu01.x / (de01.x + 1e-6f);
    const float v1 = ax.y + nu01.y / (de01.y + 1e-6f);
    const float v2 = ax.z + nu23.x / (de23.x + 1e-6f);
    const float v3 = ax.w + nu23.y / (de23.y + 1e-6f);

    float4 o;
    o.x = xv.x + fmaxf(0.f, v0 * s0 + h0);
    o.y = xv.y + fmaxf(0.f, v1 * s1 + h1);
    o.z = xv.z + fmaxf(0.f, v2 * s2 + h2);
    o.w = xv.w + fmaxf(0.f, v3 * s3 + h3);
    asm volatile("st.global.cs.v4.f32 [%0], {%1,%2,%3,%4};"
                 :: "l"(&((float4*)x_out)[i]),
                    "f"(o.x), "f"(o.y), "f"(o.z), "f"(o.w)
                 : "memory");
}

// ---------------- launch ----------------
extern "C" void kernel_launch(void* const* d_in, const int* in_sizes, int n_in,
                              void* d_out, int out_size) {
    const float* x  = (const float*)d_in[0];
    const float* e  = (const float*)d_in[1];
    const float* Aw = (const float*)d_in[2];
    const float* Ab = (const float*)d_in[3];
    const float* Bw = (const float*)d_in[4];
    const float* Bb = (const float*)d_in[5];
    const float* Cw = (const float*)d_in[6];
    const float* Cb = (const float*)d_in[7];
    const float* Dw = (const float*)d_in[8];
    const float* Db = (const float*)d_in[9];
    const float* Ew = (const float*)d_in[10];
    const float* Eb = (const float*)d_in[11];
    const float* bxg = (const float*)d_in[12];
    const float* bxb = (const float*)d_in[13];
    const float* bxm = (const float*)d_in[14];
    const float* bxv = (const float*)d_in[15];
    const float* beg = (const float*)d_in[16];
    const float* beb = (const float*)d_in[17];
    const float* bem = (const float*)d_in[18];
    const float* bev = (const float*)d_in[19];
    const void*  eidx = d_in[20];

    float* x_out = (float*)d_out;
    float* e_out = x_out + (size_t)NN * DIM;

    // launch count reduced by 1 (zero+detect merged) so edge_kernel should land
    // in ncu's "-s 5 -c 1" captured slot next profile.
    zero_detect_kernel<<<3125, 256>>>((const unsigned*)eidx);
    // weight order: 0:A 1:B 2:D 3:E 4:C
    prep_kernel<<<dim3(256, 5), 32>>>(Aw, Bw, Dw, Ew, Cw);
    node_gemm_kernel<<<dim3(782, 4), 256, SMEM_TILE>>>(x, Ab, Bb, Db, Eb);
    edge_kernel<<<10000, 256, SMEM_TILE>>>(e, Cb, eidx, beg, beb, bem, bev, e_out);
    update_kernel<<<6250, 256>>>(x, bxg, bxb, bxm, bxv, x_out);
}